// round 11
// baseline (speedup 1.0000x reference)
#include <cuda_runtime.h>
#include <cuda_bf16.h>
#include <math.h>
#include <stdint.h>

// Problem constants: B=8, S=4096, H=8, D=128, K=32
#define H_   8
#define D_   128
#define K_   32
#define NTOK 32768
#define HD   1024

typedef unsigned long long u64;

__device__ __forceinline__ uint32_t pack_bf16(float hi, float lo) {
    uint32_t r;
    asm("cvt.rn.bf16x2.f32 %0, %1, %2;" : "=r"(r) : "f"(hi), "f"(lo));
    return r;
}
static __device__ __forceinline__ uint32_t smem_u32(const void* p) {
    uint32_t a;
    asm("{ .reg .u64 t; cvta.to.shared.u64 t, %1; cvt.u32.u64 %0, t; }" : "=r"(a) : "l"(p));
    return a;
}
__device__ __forceinline__ void ldsm4(uint32_t& a0, uint32_t& a1, uint32_t& a2, uint32_t& a3,
                                      uint32_t addr) {
    asm volatile("ldmatrix.sync.aligned.m8n8.x4.shared.b16 {%0,%1,%2,%3}, [%4];"
                 : "=r"(a0), "=r"(a1), "=r"(a2), "=r"(a3) : "r"(addr));
}
__device__ __forceinline__ void mma16816(float* d, uint32_t a0, uint32_t a1, uint32_t a2,
                                         uint32_t a3, uint32_t b0, uint32_t b1) {
    asm volatile("mma.sync.aligned.m16n8k16.row.col.f32.bf16.bf16.f32 "
                 "{%0,%1,%2,%3}, {%4,%5,%6,%7}, {%8,%9}, {%0,%1,%2,%3};"
                 : "+f"(d[0]), "+f"(d[1]), "+f"(d[2]), "+f"(d[3])
                 : "r"(a0), "r"(a1), "r"(a2), "r"(a3), "r"(b0), "r"(b1));
}
// bf16x2 word -> packed f32x2 {lo<<16, hi&mask} — BOTH exact
__device__ __forceinline__ u64 pk_exact(uint32_t w) {
    u64 d;
    asm("{ .reg .b32 lo, hi; shl.b32 lo, %1, 16; and.b32 hi, %1, 0xffff0000;"
        " mov.b64 %0, {lo, hi}; }" : "=l"(d) : "r"(w));
    return d;
}
__device__ __forceinline__ u64 add2(u64 a, u64 b) {
    u64 d;
    asm("add.rn.f32x2 %0, %1, %2;" : "=l"(d) : "l"(a), "l"(b));
    return d;
}
__device__ __forceinline__ u64 ffma2(u64 a, u64 b, u64 c) {
    u64 d;
    asm("fma.rn.f32x2 %0, %1, %2, %3;" : "=l"(d) : "l"(a), "l"(b), "l"(c));
    return d;
}
__device__ __forceinline__ float2 unpack2(u64 v) {
    float2 r;
    asm("mov.b64 {%0, %1}, %2;" : "=f"(r.x), "=f"(r.y) : "l"(v));
    return r;
}

// Scratch
__device__ __nv_bfloat16 g_h[(size_t)NTOK * HD];        // 64 MB h (bf16)
__device__ float g_part[128 * 2048];                    // BN partials
__device__ float g_A[HD];
__device__ float g_C[HD];
__device__ __align__(16) __nv_bfloat16 g_wdg[H_ * 32 * 136];  // [h][k][d], stride 136
__device__ __align__(16) __nv_bfloat16 g_wut[H_ * 128 * 40];  // [h][d][k], stride 40
__device__ float g_P[H_ * K_], g_Q[H_ * K_];

// Dynamic SMEM layout for K1 (bytes)
#define SO_WDG 0          // 8704
#define SO_WUT 8704       // 10240
#define SO_BUB 18944      // 512
#define SO_P   19456      // 128
#define SO_Q   19584      // 128
#define SO_XA  19712      // 8 warps * 16*136*2 = 34816
#define SMEM_BYTES 54528

// ---------------------------------------------------------------------------
// K0: weight preprocessing. grid = 32 (4 per head), block = 128.
// ---------------------------------------------------------------------------
__global__ void __launch_bounds__(128) adapter_k0(
    const float* __restrict__ lng, const float* __restrict__ lnb,
    const float* __restrict__ wd,  const float* __restrict__ bd,
    const float* __restrict__ wu)
{
    const int h = blockIdx.x >> 2, p = blockIdx.x & 3;
    const int tid = threadIdx.x;
    for (int i = p * 1024 + tid; i < (p + 1) * 1024; i += 128) {
        int d = i >> 5, k = i & 31;                      // wd[h][d][k]
        g_wdg[h * 4352 + k * 136 + d] =
            __float2bfloat16(lng[h * 128 + d] * wd[h * 4096 + i]);
    }
    for (int i = p * 1024 + tid; i < (p + 1) * 1024; i += 128) {
        int k = i >> 7, d = i & 127;                     // wu[h][k][d]
        g_wut[h * 5120 + d * 40 + k] = __float2bfloat16(wu[h * 4096 + i]);
    }
    if (p == 0 && tid < K_) {
        float pp = 0.f, q = bd[h * K_ + tid];
        #pragma unroll 4
        for (int d = 0; d < D_; d++) {
            float v = lng[h * 128 + d] * wd[h * 4096 + d * 32 + tid];
            pp += __bfloat162float(__float2bfloat16(v));  // bf16-rounded, as GEMM sees
            q += lnb[h * 128 + d] * wd[h * 4096 + d * 32 + tid];
        }
        g_P[h * K_ + tid] = pp;
        g_Q[h * K_ + tid] = q;
    }
}

// ---------------------------------------------------------------------------
// K1: HMMA pipeline. grid = (256, H), block = 256 (8 warps). Warp: 16 tokens.
//   down[k] = rs*(S[k] - mu*P[k]) + Q[k];  S from mma on raw bf16 x.
//   h written straight from D fragments (no SMEM staging).
// ---------------------------------------------------------------------------
__global__ void __launch_bounds__(256, 3) adapter_k1(
    const float* __restrict__ x, const float* __restrict__ bu)
{
    extern __shared__ __align__(16) char smc[];
    __nv_bfloat16* wdg_s = (__nv_bfloat16*)(smc + SO_WDG);
    __nv_bfloat16* wut_s = (__nv_bfloat16*)(smc + SO_WUT);
    float* bu_s = (float*)(smc + SO_BUB);
    float* P_s  = (float*)(smc + SO_P);
    float* Q_s  = (float*)(smc + SO_Q);

    const int tid = threadIdx.x;
    const int h = blockIdx.y;

    {   // weights -> SMEM (shared by 8 warps)
        const uint4* s1 = (const uint4*)(g_wdg + h * 4352);
        uint4* d1 = (uint4*)wdg_s;
        for (int i = tid; i < 544; i += 256) d1[i] = s1[i];
        const uint4* s2 = (const uint4*)(g_wut + h * 5120);
        uint4* d2 = (uint4*)wut_s;
        for (int i = tid; i < 640; i += 256) d2[i] = s2[i];
        if (tid < 32) { P_s[tid] = g_P[h * K_ + tid]; Q_s[tid] = g_Q[h * K_ + tid]; }
        if (tid < 128) bu_s[tid] = bu[h * 128 + tid];
    }
    __syncthreads();

    const int w = tid >> 5, l = tid & 31;
    const int gr = l >> 2, gc = l & 3;
    __nv_bfloat16* xa = (__nv_bfloat16*)(smc + SO_XA) + w * (16 * 136);
    const size_t tok0 = (size_t)blockIdx.x * 128 + (size_t)w * 16;
    const float* xb = x + tok0 * HD + h * 128;

    // ---- load x -> bf16 tile (no reductions in the load loop) ----
    #pragma unroll
    for (int r = 0; r < 16; r++) {
        float4 v = *(const float4*)(xb + (size_t)r * HD + l * 4);
        *(uint2*)((char*)xa + r * 272 + l * 8) =
            make_uint2(pack_bf16(v.y, v.x), pack_bf16(v.w, v.z));
    }
    __syncwarp();

    // ---- LN stats from SMEM: lane = (row l&15, half l>>4), exact f32x2 ----
    float mu0, rs0, mu1, rs1;
    {
        const uint4* rp = (const uint4*)((const char*)xa + (l & 15) * 272 + (l >> 4) * 128);
        u64 s2 = 0ull, q2 = 0ull;
        #pragma unroll
        for (int i = 0; i < 8; i++) {
            uint4 v = rp[i];
            u64 p0 = pk_exact(v.x), p1 = pk_exact(v.y);
            u64 p2 = pk_exact(v.z), p3 = pk_exact(v.w);
            s2 = add2(s2, p0); q2 = ffma2(p0, p0, q2);
            s2 = add2(s2, p1); q2 = ffma2(p1, p1, q2);
            s2 = add2(s2, p2); q2 = ffma2(p2, p2, q2);
            s2 = add2(s2, p3); q2 = ffma2(p3, p3, q2);
        }
        float2 sf = unpack2(s2), qf = unpack2(q2);
        float s = sf.x + sf.y, q = qf.x + qf.y;
        s += __shfl_xor_sync(0xffffffffu, s, 16);
        q += __shfl_xor_sync(0xffffffffu, q, 16);
        const float mu = s * (1.f / 128.f);
        const float rs = rsqrtf(fmaxf(q * (1.f / 128.f) - mu * mu, 0.f) + 1e-5f);
        mu0 = __shfl_sync(0xffffffffu, mu, gr);
        rs0 = __shfl_sync(0xffffffffu, rs, gr);
        mu1 = __shfl_sync(0xffffffffu, mu, gr + 8);
        rs1 = __shfl_sync(0xffffffffu, rs, gr + 8);
    }

    // ---- GEMM1: D1[16 tok x 32 k] = x_tile[16x128] @ Wdg^T ----
    float D1[4][4] = {};
    {
        const uint32_t xab = smem_u32(xa);
        const int mid = l >> 3;
        const uint32_t abase = xab + ((l & 7) + ((mid & 1) << 3)) * 272 + ((mid >> 1) << 4);
        const uint32_t* wdgw = (const uint32_t*)wdg_s;
        #pragma unroll
        for (int kt = 0; kt < 8; kt++) {
            uint32_t a0, a1, a2, a3;
            ldsm4(a0, a1, a2, a3, abase + kt * 32);
            #pragma unroll
            for (int j = 0; j < 4; j++) {
                const uint32_t* bp = wdgw + (8 * j + gr) * 68 + kt * 8 + gc;
                mma16816(D1[j], a0, a1, a2, a3, bp[0], bp[4]);
            }
        }
    }

    // ---- epilogue 1: LN finalize + exact GELU; pack into GEMM2 A-frags ----
    uint32_t A2[2][4];
    #pragma unroll
    for (int j = 0; j < 4; j++) {
        const int k0 = 8 * j + 2 * gc;
        const float2 Pp = *(const float2*)(P_s + k0);
        const float2 Qp = *(const float2*)(Q_s + k0);
        float v00 = rs0 * (D1[j][0] - mu0 * Pp.x) + Qp.x;
        float v01 = rs0 * (D1[j][1] - mu0 * Pp.y) + Qp.y;
        float v10 = rs1 * (D1[j][2] - mu1 * Pp.x) + Qp.x;
        float v11 = rs1 * (D1[j][3] - mu1 * Pp.y) + Qp.y;
        v00 = 0.5f * v00 * (1.f + erff(v00 * 0.7071067811865476f));
        v01 = 0.5f * v01 * (1.f + erff(v01 * 0.7071067811865476f));
        v10 = 0.5f * v10 * (1.f + erff(v10 * 0.7071067811865476f));
        v11 = 0.5f * v11 * (1.f + erff(v11 * 0.7071067811865476f));
        A2[j >> 1][(j & 1) << 1]       = pack_bf16(v01, v00);
        A2[j >> 1][((j & 1) << 1) | 1] = pack_bf16(v11, v10);
    }

    // ---- GEMM2 (two 64-col halves) + bias + DIRECT bf16 h store ----
    const uint32_t* wutw = (const uint32_t*)wut_s;
    __nv_bfloat16* hb = g_h + tok0 * HD + h * 128;
    #pragma unroll
    for (int half = 0; half < 2; half++) {
        float D2[8][4] = {};
        #pragma unroll
        for (int j = 0; j < 8; j++) {
            const uint32_t* bp = wutw + (half * 64 + 8 * j + gr) * 20 + gc;
            mma16816(D2[j], A2[0][0], A2[0][1], A2[0][2], A2[0][3], bp[0], bp[4]);
            mma16816(D2[j], A2[1][0], A2[1][1], A2[1][2], A2[1][3], bp[8], bp[12]);
        }
        #pragma unroll
        for (int j = 0; j < 8; j++) {
            const int n0 = half * 64 + 8 * j + 2 * gc;
            const float2 bb = *(const float2*)(bu_s + n0);
            uint32_t p0 = pack_bf16(D2[j][1] + bb.y, D2[j][0] + bb.x);
            uint32_t p1 = pack_bf16(D2[j][3] + bb.y, D2[j][2] + bb.x);
            *(uint32_t*)(hb + (size_t)gr * HD + n0)       = p0;
            *(uint32_t*)(hb + (size_t)(gr + 8) * HD + n0) = p1;
        }
    }
}

// ---------------------------------------------------------------------------
// K1b: BN partial stats from stored bf16 h. grid=128, block=256.
// ---------------------------------------------------------------------------
__global__ void __launch_bounds__(256) adapter_k1b()
{
    const int b = blockIdx.x, tid = threadIdx.x;
    const uint2* hp = (const uint2*)(g_h + (size_t)b * 256 * HD) + tid;
    float s0=0,s1=0,s2=0,s3=0,q0=0,q1=0,q2=0,q3=0;
    #pragma unroll 4
    for (int t = 0; t < 256; t++) {
        uint2 v = hp[(size_t)t * 256];
        float2 f01 = __bfloat1622float2(*(const __nv_bfloat162*)&v.x);
        float2 f23 = __bfloat1622float2(*(const __nv_bfloat162*)&v.y);
        s0 += f01.x; s1 += f01.y; s2 += f23.x; s3 += f23.y;
        q0 += f01.x*f01.x; q1 += f01.y*f01.y; q2 += f23.x*f23.x; q3 += f23.y*f23.y;
    }
    float* ps = g_part + b * 2048 + tid * 4;
    ps[0] = s0; ps[1] = s1; ps[2] = s2; ps[3] = s3;
    float* pq = ps + 1024;
    pq[0] = q0; pq[1] = q1; pq[2] = q2; pq[3] = q3;
}

// ---------------------------------------------------------------------------
// K2: fold BN into affine. grid = 8, block = 1024 (8 slices x 128 features).
// ---------------------------------------------------------------------------
__global__ void __launch_bounds__(1024) adapter_k2(const float* __restrict__ bng,
                                                   const float* __restrict__ bnb)
{
    __shared__ float red[2][8][128];
    const int tid = threadIdx.x;
    const int sl = tid >> 7, fl = tid & 127;
    const int f = blockIdx.x * 128 + fl;
    float s = 0.f, q = 0.f;
    #pragma unroll
    for (int i = 0; i < 16; i++) {
        const int b = sl + i * 8;
        s += g_part[b * 2048 + f];
        q += g_part[b * 2048 + 1024 + f];
    }
    red[0][sl][fl] = s;
    red[1][sl][fl] = q;
    __syncthreads();
    if (sl == 0) {
        float S = 0.f, Q = 0.f;
        #pragma unroll
        for (int j = 0; j < 8; j++) { S += red[0][j][fl]; Q += red[1][j][fl]; }
        const float inv = 1.f / (float)NTOK;
        const float mu  = S * inv;
        const float var = fmaxf(Q * inv - mu * mu, 0.f);
        const float rsv = rsqrtf(var + 1e-5f);
        const float g = bng[f], bb = bnb[f];
        g_A[f] = 0.1f * g * rsv;
        g_C[f] = 0.1f * (bb - mu * rsv * g);
    }
}

// ---------------------------------------------------------------------------
// K3: out = h*A + C + x (h is bf16; streaming).
// ---------------------------------------------------------------------------
__global__ void __launch_bounds__(256) adapter_k3(const float* __restrict__ x,
                                                  float* __restrict__ out)
{
    const size_t i = (size_t)blockIdx.x * 256 + threadIdx.x;
    const uint2 hraw = ((const uint2*)g_h)[i];
    const float4 xv = ((const float4*)x)[i];
    float2 f01 = __bfloat1622float2(*(const __nv_bfloat162*)&hraw.x);
    float2 f23 = __bfloat1622float2(*(const __nv_bfloat162*)&hraw.y);
    const int col = (int)((i * 4) & (HD - 1));
    const float4 a = *(const float4*)(g_A + col);
    const float4 c = *(const float4*)(g_C + col);
    float4 r;
    r.x = f01.x * a.x + c.x + xv.x;
    r.y = f01.y * a.y + c.y + xv.y;
    r.z = f23.x * a.z + c.z + xv.z;
    r.w = f23.y * a.w + c.w + xv.w;
    ((float4*)out)[i] = r;
}

// ---------------------------------------------------------------------------
extern "C" void kernel_launch(void* const* d_in, const int* in_sizes, int n_in,
                              void* d_out, int out_size)
{
    const float* x   = (const float*)d_in[0];
    const float* lng = (const float*)d_in[1];
    const float* lnb = (const float*)d_in[2];
    const float* wd  = (const float*)d_in[3];
    const float* bd  = (const float*)d_in[4];
    const float* wu  = (const float*)d_in[5];
    const float* bu  = (const float*)d_in[6];
    const float* bng = (const float*)d_in[7];
    const float* bnb = (const float*)d_in[8];
    float* out = (float*)d_out;

    cudaFuncSetAttribute(adapter_k1, cudaFuncAttributeMaxDynamicSharedMemorySize, SMEM_BYTES);

    adapter_k0<<<32, 128>>>(lng, lnb, wd, bd, wu);
    adapter_k1<<<dim3(256, H_), 256, SMEM_BYTES>>>(x, bu);
    adapter_k1b<<<128, 256>>>();
    adapter_k2<<<8, 1024>>>(bng, bnb);
    adapter_k3<<<(NTOK * HD) / (256 * 4), 256>>>(x, out);
}

// round 12
// speedup vs baseline: 1.3460x; 1.3460x over previous
#include <cuda_runtime.h>
#include <cuda_bf16.h>
#include <math.h>
#include <stdint.h>

// Problem constants: B=8, S=4096, H=8, D=128, K=32
#define H_   8
#define D_   128
#define K_   32
#define NTOK 32768
#define HD   1024

typedef unsigned long long u64;

__device__ __forceinline__ uint32_t pack_bf16(float hi, float lo) {
    uint32_t r;
    asm("cvt.rn.bf16x2.f32 %0, %1, %2;" : "=r"(r) : "f"(hi), "f"(lo));
    return r;
}
static __device__ __forceinline__ uint32_t smem_u32(const void* p) {
    uint32_t a;
    asm("{ .reg .u64 t; cvta.to.shared.u64 t, %1; cvt.u32.u64 %0, t; }" : "=r"(a) : "l"(p));
    return a;
}
__device__ __forceinline__ void ldsm4(uint32_t& a0, uint32_t& a1, uint32_t& a2, uint32_t& a3,
                                      uint32_t addr) {
    asm volatile("ldmatrix.sync.aligned.m8n8.x4.shared.b16 {%0,%1,%2,%3}, [%4];"
                 : "=r"(a0), "=r"(a1), "=r"(a2), "=r"(a3) : "r"(addr));
}
__device__ __forceinline__ void mma16816(float* d, uint32_t a0, uint32_t a1, uint32_t a2,
                                         uint32_t a3, uint32_t b0, uint32_t b1) {
    asm volatile("mma.sync.aligned.m16n8k16.row.col.f32.bf16.bf16.f32 "
                 "{%0,%1,%2,%3}, {%4,%5,%6,%7}, {%8,%9}, {%0,%1,%2,%3};"
                 : "+f"(d[0]), "+f"(d[1]), "+f"(d[2]), "+f"(d[3])
                 : "r"(a0), "r"(a1), "r"(a2), "r"(a3), "r"(b0), "r"(b1));
}
// bf16x2 word -> packed f32x2 {lo<<16, hi&mask} — BOTH exact
__device__ __forceinline__ u64 pk_exact(uint32_t w) {
    u64 d;
    asm("{ .reg .b32 lo, hi; shl.b32 lo, %1, 16; and.b32 hi, %1, 0xffff0000;"
        " mov.b64 %0, {lo, hi}; }" : "=l"(d) : "r"(w));
    return d;
}
__device__ __forceinline__ u64 add2(u64 a, u64 b) {
    u64 d;
    asm("add.rn.f32x2 %0, %1, %2;" : "=l"(d) : "l"(a), "l"(b));
    return d;
}
__device__ __forceinline__ u64 ffma2(u64 a, u64 b, u64 c) {
    u64 d;
    asm("fma.rn.f32x2 %0, %1, %2, %3;" : "=l"(d) : "l"(a), "l"(b), "l"(c));
    return d;
}
__device__ __forceinline__ float2 unpack2(u64 v) {
    float2 r;
    asm("mov.b64 {%0, %1}, %2;" : "=f"(r.x), "=f"(r.y) : "l"(v));
    return r;
}

// Scratch
__device__ __nv_bfloat16 g_h[(size_t)NTOK * HD];        // 64 MB h (bf16)
__device__ float g_part[H_ * 256 * 256];                // per-(head,block) BN partials
__device__ float g_A[HD];
__device__ float g_C[HD];
__device__ __align__(16) __nv_bfloat16 g_wdg[H_ * 32 * 136];  // [h][k][d], stride 136
__device__ __align__(16) __nv_bfloat16 g_wut[H_ * 128 * 40];  // [h][d][k], stride 40
__device__ float g_P[H_ * K_], g_Q[H_ * K_];

// Dynamic SMEM layout for K1 (bytes)
#define SO_WDG 0          // 8704
#define SO_WUT 8704       // 10240
#define SO_BUB 18944      // 512
#define SO_P   19456      // 128
#define SO_Q   19584      // 128
#define SO_XA  19712      // 8 warps * 16*136*2 = 34816
#define SO_ST  54528      // 8 warps * 256 floats = 8192 (BN partials)
#define SMEM_BYTES 62720

// ---------------------------------------------------------------------------
// K0: weight preprocessing. grid = 32 (4 per head), block = 128.
// ---------------------------------------------------------------------------
__global__ void __launch_bounds__(128) adapter_k0(
    const float* __restrict__ lng, const float* __restrict__ lnb,
    const float* __restrict__ wd,  const float* __restrict__ bd,
    const float* __restrict__ wu)
{
    const int h = blockIdx.x >> 2, p = blockIdx.x & 3;
    const int tid = threadIdx.x;
    for (int i = p * 1024 + tid; i < (p + 1) * 1024; i += 128) {
        int d = i >> 5, k = i & 31;                      // wd[h][d][k]
        g_wdg[h * 4352 + k * 136 + d] =
            __float2bfloat16(lng[h * 128 + d] * wd[h * 4096 + i]);
    }
    for (int i = p * 1024 + tid; i < (p + 1) * 1024; i += 128) {
        int k = i >> 7, d = i & 127;                     // wu[h][k][d]
        g_wut[h * 5120 + d * 40 + k] = __float2bfloat16(wu[h * 4096 + i]);
    }
    if (p == 0 && tid < K_) {
        float pp = 0.f, q = bd[h * K_ + tid];
        #pragma unroll 4
        for (int d = 0; d < D_; d++) {
            float v = lng[h * 128 + d] * wd[h * 4096 + d * 32 + tid];
            pp += __bfloat162float(__float2bfloat16(v));  // bf16-rounded, as GEMM sees
            q += lnb[h * 128 + d] * wd[h * 4096 + d * 32 + tid];
        }
        g_P[h * K_ + tid] = pp;
        g_Q[h * K_ + tid] = q;
    }
}

// ---------------------------------------------------------------------------
// K1: HMMA pipeline + fused BN partials. grid = (256, H), block = 256 (8 warps).
//   down[k] = rs*(S[k] - mu*P[k]) + Q[k];  S from mma on raw bf16 x.
// ---------------------------------------------------------------------------
__global__ void __launch_bounds__(256, 3) adapter_k1(
    const float* __restrict__ x, const float* __restrict__ bu)
{
    extern __shared__ __align__(16) char smc[];
    __nv_bfloat16* wdg_s = (__nv_bfloat16*)(smc + SO_WDG);
    __nv_bfloat16* wut_s = (__nv_bfloat16*)(smc + SO_WUT);
    float* bu_s = (float*)(smc + SO_BUB);
    float* P_s  = (float*)(smc + SO_P);
    float* Q_s  = (float*)(smc + SO_Q);
    float* st_s = (float*)(smc + SO_ST);

    const int tid = threadIdx.x;
    const int h = blockIdx.y;

    {   // weights -> SMEM (shared by 8 warps)
        const uint4* s1 = (const uint4*)(g_wdg + h * 4352);
        uint4* d1 = (uint4*)wdg_s;
        for (int i = tid; i < 544; i += 256) d1[i] = s1[i];
        const uint4* s2 = (const uint4*)(g_wut + h * 5120);
        uint4* d2 = (uint4*)wut_s;
        for (int i = tid; i < 640; i += 256) d2[i] = s2[i];
        if (tid < 32) { P_s[tid] = g_P[h * K_ + tid]; Q_s[tid] = g_Q[h * K_ + tid]; }
        if (tid < 128) bu_s[tid] = bu[h * 128 + tid];
    }
    __syncthreads();

    const int w = tid >> 5, l = tid & 31;
    const int gr = l >> 2, gc = l & 3;
    __nv_bfloat16* xa = (__nv_bfloat16*)(smc + SO_XA) + w * (16 * 136);
    uint32_t* xaw = (uint32_t*)xa;
    const size_t tok0 = (size_t)blockIdx.x * 128 + (size_t)w * 16;
    const float* xb = x + tok0 * HD + h * 128;

    // ---- load x -> bf16 tile (no reductions in the load loop) ----
    #pragma unroll
    for (int r = 0; r < 16; r++) {
        float4 v = *(const float4*)(xb + (size_t)r * HD + l * 4);
        *(uint2*)((char*)xa + r * 272 + l * 8) =
            make_uint2(pack_bf16(v.y, v.x), pack_bf16(v.w, v.z));
    }
    __syncwarp();

    // ---- LN stats from SMEM: lane = (row l&15, half l>>4), exact f32x2 ----
    float mu0, rs0, mu1, rs1;
    {
        const uint4* rp = (const uint4*)((const char*)xa + (l & 15) * 272 + (l >> 4) * 128);
        u64 s2 = 0ull, q2 = 0ull;
        #pragma unroll
        for (int i = 0; i < 8; i++) {
            uint4 v = rp[i];
            u64 p0 = pk_exact(v.x), p1 = pk_exact(v.y);
            u64 p2 = pk_exact(v.z), p3 = pk_exact(v.w);
            s2 = add2(s2, p0); q2 = ffma2(p0, p0, q2);
            s2 = add2(s2, p1); q2 = ffma2(p1, p1, q2);
            s2 = add2(s2, p2); q2 = ffma2(p2, p2, q2);
            s2 = add2(s2, p3); q2 = ffma2(p3, p3, q2);
        }
        float2 sf = unpack2(s2), qf = unpack2(q2);
        float s = sf.x + sf.y, q = qf.x + qf.y;
        s += __shfl_xor_sync(0xffffffffu, s, 16);
        q += __shfl_xor_sync(0xffffffffu, q, 16);
        const float mu = s * (1.f / 128.f);
        const float rs = rsqrtf(fmaxf(q * (1.f / 128.f) - mu * mu, 0.f) + 1e-5f);
        mu0 = __shfl_sync(0xffffffffu, mu, gr);
        rs0 = __shfl_sync(0xffffffffu, rs, gr);
        mu1 = __shfl_sync(0xffffffffu, mu, gr + 8);
        rs1 = __shfl_sync(0xffffffffu, rs, gr + 8);
    }

    // ---- GEMM1: D1[16 tok x 32 k] = x_tile[16x128] @ Wdg^T ----
    float D1[4][4] = {};
    {
        const uint32_t xab = smem_u32(xa);
        const int mid = l >> 3;
        const uint32_t abase = xab + ((l & 7) + ((mid & 1) << 3)) * 272 + ((mid >> 1) << 4);
        const uint32_t* wdgw = (const uint32_t*)wdg_s;
        #pragma unroll
        for (int kt = 0; kt < 8; kt++) {
            uint32_t a0, a1, a2, a3;
            ldsm4(a0, a1, a2, a3, abase + kt * 32);
            #pragma unroll
            for (int j = 0; j < 4; j++) {
                const uint32_t* bp = wdgw + (8 * j + gr) * 68 + kt * 8 + gc;
                mma16816(D1[j], a0, a1, a2, a3, bp[0], bp[4]);
            }
        }
    }

    // ---- epilogue 1: LN finalize + exact GELU; pack into GEMM2 A-frags ----
    uint32_t A2[2][4];
    #pragma unroll
    for (int j = 0; j < 4; j++) {
        const int k0 = 8 * j + 2 * gc;
        const float2 Pp = *(const float2*)(P_s + k0);
        const float2 Qp = *(const float2*)(Q_s + k0);
        float v00 = rs0 * (D1[j][0] - mu0 * Pp.x) + Qp.x;
        float v01 = rs0 * (D1[j][1] - mu0 * Pp.y) + Qp.y;
        float v10 = rs1 * (D1[j][2] - mu1 * Pp.x) + Qp.x;
        float v11 = rs1 * (D1[j][3] - mu1 * Pp.y) + Qp.y;
        v00 = 0.5f * v00 * (1.f + erff(v00 * 0.7071067811865476f));
        v01 = 0.5f * v01 * (1.f + erff(v01 * 0.7071067811865476f));
        v10 = 0.5f * v10 * (1.f + erff(v10 * 0.7071067811865476f));
        v11 = 0.5f * v11 * (1.f + erff(v11 * 0.7071067811865476f));
        A2[j >> 1][(j & 1) << 1]       = pack_bf16(v01, v00);
        A2[j >> 1][((j & 1) << 1) | 1] = pack_bf16(v11, v10);
    }

    // ---- GEMM2 (two 64-col halves) + bias + staged h store + BN partials ----
    const uint32_t* wutw = (const uint32_t*)wut_s;
    __nv_bfloat16* hb = g_h + tok0 * HD + h * 128;
    float* stw = st_s + w * 256;
    #pragma unroll
    for (int half = 0; half < 2; half++) {
        float D2[8][4] = {};
        #pragma unroll
        for (int j = 0; j < 8; j++) {
            const uint32_t* bp = wutw + (half * 64 + 8 * j + gr) * 20 + gc;
            mma16816(D2[j], A2[0][0], A2[0][1], A2[0][2], A2[0][3], bp[0], bp[4]);
            mma16816(D2[j], A2[1][0], A2[1][1], A2[1][2], A2[1][3], bp[8], bp[12]);
        }
        __syncwarp();   // x tile fully consumed before overwrite
        #pragma unroll
        for (int j = 0; j < 8; j++) {
            const int n0 = half * 64 + 8 * j + 2 * gc;
            const float2 bb = *(const float2*)(bu_s + n0);
            uint32_t p0 = pack_bf16(D2[j][1] + bb.y, D2[j][0] + bb.x);
            uint32_t p1 = pack_bf16(D2[j][3] + bb.y, D2[j][2] + bb.x);
            xaw[gr * 68 + half * 32 + 4 * j + gc]       = p0;
            xaw[(gr + 8) * 68 + half * 32 + 4 * j + gc] = p1;
        }
        __syncwarp();
        // coalesced h store + per-lane BN partials (4 features x 8 rows)
        float s0=0,s1=0,s2=0,s3=0,q0=0,q1=0,q2=0,q3=0;
        const int c = l & 15;
        #pragma unroll
        for (int i = 0; i < 8; i++) {
            const int r = i * 2 + (l >> 4);
            uint2 v = *(const uint2*)(xaw + r * 68 + half * 32 + c * 2);
            *(uint2*)(hb + (size_t)r * HD + half * 64 + c * 4) = v;
            float2 f01 = __bfloat1622float2(*(const __nv_bfloat162*)&v.x);
            float2 f23 = __bfloat1622float2(*(const __nv_bfloat162*)&v.y);
            s0 += f01.x; s1 += f01.y; s2 += f23.x; s3 += f23.y;
            q0 += f01.x*f01.x; q1 += f01.y*f01.y; q2 += f23.x*f23.x; q3 += f23.y*f23.y;
        }
        // combine the two row-parities (lane l with l^16 share features)
        s0 += __shfl_xor_sync(0xffffffffu, s0, 16);
        s1 += __shfl_xor_sync(0xffffffffu, s1, 16);
        s2 += __shfl_xor_sync(0xffffffffu, s2, 16);
        s3 += __shfl_xor_sync(0xffffffffu, s3, 16);
        q0 += __shfl_xor_sync(0xffffffffu, q0, 16);
        q1 += __shfl_xor_sync(0xffffffffu, q1, 16);
        q2 += __shfl_xor_sync(0xffffffffu, q2, 16);
        q3 += __shfl_xor_sync(0xffffffffu, q3, 16);
        if (l < 16) {
            *(float4*)(stw + half * 64 + c * 4)       = make_float4(s0, s1, s2, s3);
            *(float4*)(stw + 128 + half * 64 + c * 4) = make_float4(q0, q1, q2, q3);
        }
        __syncwarp();
    }
    __syncthreads();

    // deterministic block reduce over 8 warps -> per-(head,block) partials
    float a2 = 0.f;
    #pragma unroll
    for (int w2 = 0; w2 < 8; w2++) a2 += st_s[w2 * 256 + tid];
    g_part[((size_t)h * 256 + blockIdx.x) * 256 + tid] = a2;
}

// ---------------------------------------------------------------------------
// K2: fold BN into affine. grid = H, block = 1024 (8 slices x 128 features).
// ---------------------------------------------------------------------------
__global__ void __launch_bounds__(1024) adapter_k2(const float* __restrict__ bng,
                                                   const float* __restrict__ bnb)
{
    __shared__ float red[2][8][128];
    const int tid = threadIdx.x;
    const int sl = tid >> 7, fl = tid & 127;
    const int h = blockIdx.x;
    float s = 0.f, q = 0.f;
    #pragma unroll 4
    for (int i = 0; i < 32; i++) {
        const int b = sl + i * 8;
        s += g_part[((size_t)h * 256 + b) * 256 + fl];
        q += g_part[((size_t)h * 256 + b) * 256 + 128 + fl];
    }
    red[0][sl][fl] = s;
    red[1][sl][fl] = q;
    __syncthreads();
    if (sl == 0) {
        float S = 0.f, Q = 0.f;
        #pragma unroll
        for (int j = 0; j < 8; j++) { S += red[0][j][fl]; Q += red[1][j][fl]; }
        const int f = h * 128 + fl;
        const float inv = 1.f / (float)NTOK;
        const float mu  = S * inv;
        const float var = fmaxf(Q * inv - mu * mu, 0.f);
        const float rsv = rsqrtf(var + 1e-5f);
        const float g = bng[f], bb = bnb[f];
        g_A[f] = 0.1f * g * rsv;
        g_C[f] = 0.1f * (bb - mu * rsv * g);
    }
}

// ---------------------------------------------------------------------------
// K3: out = h*A + C + x (h is bf16; streaming).
// ---------------------------------------------------------------------------
__global__ void __launch_bounds__(256) adapter_k3(const float* __restrict__ x,
                                                  float* __restrict__ out)
{
    const size_t i = (size_t)blockIdx.x * 256 + threadIdx.x;
    const uint2 hraw = ((const uint2*)g_h)[i];
    const float4 xv = ((const float4*)x)[i];
    float2 f01 = __bfloat1622float2(*(const __nv_bfloat162*)&hraw.x);
    float2 f23 = __bfloat1622float2(*(const __nv_bfloat162*)&hraw.y);
    const int col = (int)((i * 4) & (HD - 1));
    const float4 a = *(const float4*)(g_A + col);
    const float4 c = *(const float4*)(g_C + col);
    float4 r;
    r.x = f01.x * a.x + c.x + xv.x;
    r.y = f01.y * a.y + c.y + xv.y;
    r.z = f23.x * a.z + c.z + xv.z;
    r.w = f23.y * a.w + c.w + xv.w;
    ((float4*)out)[i] = r;
}

// ---------------------------------------------------------------------------
extern "C" void kernel_launch(void* const* d_in, const int* in_sizes, int n_in,
                              void* d_out, int out_size)
{
    const float* x   = (const float*)d_in[0];
    const float* lng = (const float*)d_in[1];
    const float* lnb = (const float*)d_in[2];
    const float* wd  = (const float*)d_in[3];
    const float* bd  = (const float*)d_in[4];
    const float* wu  = (const float*)d_in[5];
    const float* bu  = (const float*)d_in[6];
    const float* bng = (const float*)d_in[7];
    const float* bnb = (const float*)d_in[8];
    float* out = (float*)d_out;

    cudaFuncSetAttribute(adapter_k1, cudaFuncAttributeMaxDynamicSharedMemorySize, SMEM_BYTES);

    adapter_k0<<<32, 128>>>(lng, lnb, wd, bd, wu);
    adapter_k1<<<dim3(256, H_), 256, SMEM_BYTES>>>(x, bu);
    adapter_k2<<<H_, 1024>>>(bng, bnb);
    adapter_k3<<<(NTOK * HD) / (256 * 4), 256>>>(x, out);
}